// round 4
// baseline (speedup 1.0000x reference)
#include <cuda_runtime.h>

#define N_NODES 100000
#define N_EDGES 1600000
#define HID 128
#define NUM_LAYERS 10
#define NUM_GRAPHS 64
#define NUM_CLASSES 2

// ---------------- scratch (device globals; no runtime allocation) ----------------
__device__ __align__(16) float g_x[(size_t)N_NODES * HID];
__device__ __align__(16) float g_h[(size_t)N_NODES * HID];
__device__ int   g_deg[N_NODES];
__device__ int   g_rowptr[N_NODES + 1];
__device__ int   g_fill[N_NODES];
__device__ int   g_ssrc[N_EDGES];
__device__ int   g_bsums[256];
__device__ __align__(16) float g_pool[NUM_GRAPHS * HID];
__device__ float g_cnt[NUM_GRAPHS];
__device__ __align__(16) float g_cls[NUM_GRAPHS * HID];

// ---------------- CSR build ----------------
__global__ void zero_kernel() {
    int i = blockIdx.x * blockDim.x + threadIdx.x;
    if (i < N_NODES) g_deg[i] = 0;
    if (i < NUM_GRAPHS * HID) g_pool[i] = 0.f;
    if (i < NUM_GRAPHS) g_cnt[i] = 0.f;
}

__global__ void hist_kernel(const int* __restrict__ dst) {
    int e = blockIdx.x * blockDim.x + threadIdx.x;
    if (e < N_EDGES) atomicAdd(&g_deg[dst[e]], 1);
}

// block-wise inclusive scan (512/block), emits exclusive values + block sums
__global__ void scan1_kernel() {
    __shared__ int s[512];
    int tid = threadIdx.x;
    int i = blockIdx.x * 512 + tid;
    int v = (i < N_NODES) ? g_deg[i] : 0;
    s[tid] = v;
    __syncthreads();
    for (int off = 1; off < 512; off <<= 1) {
        int add = (tid >= off) ? s[tid - off] : 0;
        __syncthreads();
        s[tid] += add;
        __syncthreads();
    }
    if (i < N_NODES) g_rowptr[i] = s[tid] - v;  // exclusive
    if (tid == 511) g_bsums[blockIdx.x] = s[511];
}

__global__ void scan2_kernel(int nblk) {
    __shared__ int s[256];
    int tid = threadIdx.x;
    int v = (tid < nblk) ? g_bsums[tid] : 0;
    s[tid] = v;
    __syncthreads();
    for (int off = 1; off < 256; off <<= 1) {
        int add = (tid >= off) ? s[tid - off] : 0;
        __syncthreads();
        s[tid] += add;
        __syncthreads();
    }
    if (tid < nblk) g_bsums[tid] = s[tid] - v;  // exclusive over block sums
}

__global__ void scan3_kernel() {
    int i = blockIdx.x * blockDim.x + threadIdx.x;
    if (i < N_NODES) {
        int rp = g_rowptr[i] + g_bsums[i >> 9];
        g_rowptr[i] = rp;
        g_fill[i] = rp;
    }
    if (i == 0) g_rowptr[N_NODES] = N_EDGES;
}

__global__ void scatter_kernel(const int* __restrict__ src,
                               const int* __restrict__ dst) {
    int e = blockIdx.x * blockDim.x + threadIdx.x;
    if (e < N_EDGES) {
        int d = dst[e];
        int p = atomicAdd(&g_fill[d], 1);
        g_ssrc[p] = src[e];
    }
}

// ---------------- per-layer aggregation: h[v] = (1+eps)*x[v] + sum_in x[u] --------
__global__ void aggr_kernel(const float* __restrict__ xin_ext,
                            const float* __restrict__ eps, int layer, int use_gx) {
    int gw = (blockIdx.x * blockDim.x + threadIdx.x) >> 5;
    int lane = threadIdx.x & 31;
    if (gw >= N_NODES) return;
    const float* x = use_gx ? g_x : xin_ext;
    float ep1 = 1.0f + eps[layer];
    const float4* xv = (const float4*)x;
    float4 b = __ldg(&xv[(size_t)gw * 32 + lane]);
    float4 a0 = make_float4(b.x * ep1, b.y * ep1, b.z * ep1, b.w * ep1);
    float4 a1 = make_float4(0.f, 0.f, 0.f, 0.f);
    float4 a2 = a1, a3 = a1;
    int s = g_rowptr[gw], e = g_rowptr[gw + 1];
    int i = s;
    for (; i + 4 <= e; i += 4) {
        int s0 = g_ssrc[i], s1 = g_ssrc[i + 1], s2 = g_ssrc[i + 2], s3 = g_ssrc[i + 3];
        float4 v0 = __ldg(&xv[(size_t)s0 * 32 + lane]);
        float4 v1 = __ldg(&xv[(size_t)s1 * 32 + lane]);
        float4 v2 = __ldg(&xv[(size_t)s2 * 32 + lane]);
        float4 v3 = __ldg(&xv[(size_t)s3 * 32 + lane]);
        a0.x += v0.x; a0.y += v0.y; a0.z += v0.z; a0.w += v0.w;
        a1.x += v1.x; a1.y += v1.y; a1.z += v1.z; a1.w += v1.w;
        a2.x += v2.x; a2.y += v2.y; a2.z += v2.z; a2.w += v2.w;
        a3.x += v3.x; a3.y += v3.y; a3.z += v3.z; a3.w += v3.w;
    }
    for (; i < e; i++) {
        int s0 = g_ssrc[i];
        float4 v0 = __ldg(&xv[(size_t)s0 * 32 + lane]);
        a1.x += v0.x; a1.y += v0.y; a1.z += v0.z; a1.w += v0.w;
    }
    a0.x += a1.x + a2.x + a3.x;
    a0.y += a1.y + a2.y + a3.y;
    a0.z += a1.z + a2.z + a3.z;
    a0.w += a1.w + a2.w + a3.w;
    ((float4*)g_h)[(size_t)gw * 32 + lane] = a0;
}

// ---------------- fused MLP: g_x = relu(relu(h@W1+b1)@W2 + b2 [+h]) + xin ---------
// BM=32 rows/block; static shared only (<=48KB); W1/W2 streamed from L2 via __ldg.
#define BM 32
#define HSTR 132  // padded row stride in floats

__global__ void __launch_bounds__(256)
mlp_kernel(const float* __restrict__ xin_ext,
           const float* __restrict__ W1, const float* __restrict__ b1,
           const float* __restrict__ W2, const float* __restrict__ b2,
           int add_h, int use_gx) {
    __shared__ float Hs[BM * HSTR];
    __shared__ float Ts[BM * HSTR];

    const float* xin = use_gx ? g_x : xin_ext;
    int t = threadIdx.x;
    int row0 = blockIdx.x * BM;
    int nrows = N_NODES - row0; if (nrows > BM) nrows = BM;

    // load H tile (BM x 128) into shared
    for (int i = t; i < BM * 32; i += 256) {
        int r = i >> 5, c = i & 31;
        float4 v = (r < nrows)
            ? *((const float4*)(g_h + (size_t)(row0 + r) * HID) + c)
            : make_float4(0.f, 0.f, 0.f, 0.f);
        *((float4*)&Hs[r * HSTR + c * 4]) = v;
    }
    __syncthreads();

    int tx = t & 15, ty = t >> 4;   // 16 x 16 thread grid
    int cb = tx * 8;                // 8 cols per thread
    int rb = ty * 2;                // 2 rows per thread

    float acc[2][8];
#pragma unroll
    for (int r = 0; r < 2; r++)
#pragma unroll
        for (int c = 0; c < 8; c++) acc[r][c] = 0.f;

#pragma unroll 4
    for (int k = 0; k < 128; k++) {
        float a0 = Hs[rb * HSTR + k];
        float a1 = Hs[(rb + 1) * HSTR + k];
        float4 w0 = __ldg((const float4*)&W1[k * 128 + cb]);
        float4 w1 = __ldg((const float4*)&W1[k * 128 + cb + 4]);
        float bv[8] = {w0.x, w0.y, w0.z, w0.w, w1.x, w1.y, w1.z, w1.w};
#pragma unroll
        for (int c = 0; c < 8; c++) { acc[0][c] += a0 * bv[c]; acc[1][c] += a1 * bv[c]; }
    }
#pragma unroll
    for (int r = 0; r < 2; r++)
#pragma unroll
        for (int c = 0; c < 8; c++) {
            float v = acc[r][c] + __ldg(&b1[cb + c]);
            Ts[(rb + r) * HSTR + cb + c] = fmaxf(v, 0.f);
        }
    __syncthreads();

#pragma unroll
    for (int r = 0; r < 2; r++)
#pragma unroll
        for (int c = 0; c < 8; c++) acc[r][c] = 0.f;

#pragma unroll 4
    for (int k = 0; k < 128; k++) {
        float a0 = Ts[rb * HSTR + k];
        float a1 = Ts[(rb + 1) * HSTR + k];
        float4 w0 = __ldg((const float4*)&W2[k * 128 + cb]);
        float4 w1 = __ldg((const float4*)&W2[k * 128 + cb + 4]);
        float bv[8] = {w0.x, w0.y, w0.z, w0.w, w1.x, w1.y, w1.z, w1.w};
#pragma unroll
        for (int c = 0; c < 8; c++) { acc[0][c] += a0 * bv[c]; acc[1][c] += a1 * bv[c]; }
    }

#pragma unroll
    for (int r = 0; r < 2; r++) {
        int row = rb + r;
        if (row < nrows) {
#pragma unroll
            for (int c = 0; c < 8; c++) {
                int col = cb + c;
                float v = acc[r][c] + __ldg(&b2[col]);
                if (add_h) v += Hs[row * HSTR + col];
                v = fmaxf(v, 0.f) + xin[(size_t)(row0 + row) * HID + col];
                g_x[(size_t)(row0 + row) * HID + col] = v;
            }
        }
    }
}

// ---------------- mean pool over sorted batch ----------------
#define POOL_CHUNK 256
__global__ void pool_kernel(const int* __restrict__ batch) {
    int d = threadIdx.x;  // 128
    int n0 = blockIdx.x * POOL_CHUNK;
    int n1 = n0 + POOL_CHUNK; if (n1 > N_NODES) n1 = N_NODES;
    int cur = batch[n0];
    float local = 0.f;
    for (int n = n0; n < n1; n++) {
        int b = batch[n];
        if (b != cur) {
            atomicAdd(&g_pool[cur * HID + d], local);
            local = 0.f; cur = b;
        }
        local += g_x[(size_t)n * HID + d];
    }
    atomicAdd(&g_pool[cur * HID + d], local);
    if (d == 0) {
        int c2 = batch[n0];
        float cl = 0.f;
        for (int n = n0; n < n1; n++) {
            int b = batch[n];
            if (b != c2) { atomicAdd(&g_cnt[c2], cl); cl = 0.f; c2 = b; }
            cl += 1.f;
        }
        atomicAdd(&g_cnt[c2], cl);
    }
}

// ---------------- classifier (two small kernels, static smem only) ----------------
__global__ void cls1_kernel(const float* __restrict__ Wc1,
                            const float* __restrict__ bc1) {
    __shared__ float Ps[128];
    int g = blockIdx.x;     // 64 blocks
    int t = threadIdx.x;    // 128 threads
    float inv = 1.f / fmaxf(g_cnt[g], 1.f);
    Ps[t] = g_pool[g * HID + t] * inv;
    __syncthreads();
    float s = bc1[t];
#pragma unroll 4
    for (int k = 0; k < 128; k++) s += Ps[k] * __ldg(&Wc1[k * 128 + t]);
    g_cls[g * HID + t] = fmaxf(s, 0.f);
}

__global__ void cls2_kernel(const float* __restrict__ Wc2,
                            const float* __restrict__ bc2,
                            float* __restrict__ out) {
    int t = threadIdx.x;  // 128 = 64 graphs * 2 classes
    int g = t >> 1, c = t & 1;
    float s = bc2[c];
#pragma unroll 4
    for (int k = 0; k < 128; k++) s += g_cls[g * HID + k] * __ldg(&Wc2[k * 2 + c]);
    out[t] = s;
}

// ---------------- launch (pure kernel launches — graph-capture safe) -------------
extern "C" void kernel_launch(void* const* d_in, const int* in_sizes, int n_in,
                              void* d_out, int out_size) {
    const float* x     = (const float*)d_in[0];
    const int*   ei    = (const int*)d_in[1];     // int32 (JAX x64 disabled)
    const int*   batch = (const int*)d_in[2];     // int32
    const float* eps   = (const float*)d_in[3];
    const float* W1    = (const float*)d_in[4];
    const float* b1    = (const float*)d_in[5];
    const float* W2    = (const float*)d_in[6];
    const float* b2    = (const float*)d_in[7];
    const float* Wc1   = (const float*)d_in[8];
    const float* bc1   = (const float*)d_in[9];
    const float* Wc2   = (const float*)d_in[10];
    const float* bc2   = (const float*)d_in[11];
    const int* src = ei;
    const int* dst = ei + N_EDGES;

    const int nblk_scan = (N_NODES + 511) / 512;  // 196

    zero_kernel<<<(N_NODES + 255) / 256, 256>>>();
    hist_kernel<<<(N_EDGES + 255) / 256, 256>>>(dst);
    scan1_kernel<<<nblk_scan, 512>>>();
    scan2_kernel<<<1, 256>>>(nblk_scan);
    scan3_kernel<<<(N_NODES + 255) / 256, 256>>>();
    scatter_kernel<<<(N_EDGES + 255) / 256, 256>>>(src, dst);

    for (int i = 0; i < NUM_LAYERS; i++) {
        int use_gx = (i > 0) ? 1 : 0;
        aggr_kernel<<<(N_NODES + 7) / 8, 256>>>(x, eps, i, use_gx);
        mlp_kernel<<<(N_NODES + BM - 1) / BM, 256>>>(
            x,
            W1 + (size_t)i * HID * HID, b1 + (size_t)i * HID,
            W2 + (size_t)i * HID * HID, b2 + (size_t)i * HID,
            (i > 0) ? 1 : 0, use_gx);
    }

    pool_kernel<<<(N_NODES + POOL_CHUNK - 1) / POOL_CHUNK, 128>>>(batch);
    cls1_kernel<<<NUM_GRAPHS, 128>>>(Wc1, bc1);
    cls2_kernel<<<1, 128>>>(Wc2, bc2, (float*)d_out);
}

// round 6
// speedup vs baseline: 1.4708x; 1.4708x over previous
#include <cuda_runtime.h>

#define N_NODES 100000
#define N_EDGES 1600000
#define HID 128
#define NUM_LAYERS 10
#define NUM_GRAPHS 64
#define NUM_CLASSES 2

// ---------------- scratch (device globals; no runtime allocation) ----------------
__device__ __align__(16) float g_x[(size_t)N_NODES * HID];
__device__ __align__(16) float g_h[(size_t)N_NODES * HID];
__device__ int   g_deg[N_NODES];
__device__ int   g_rowptr[N_NODES + 1];
__device__ int   g_fill[N_NODES];
__device__ int   g_ssrc[N_EDGES];
__device__ int   g_bsums[256];
__device__ __align__(16) float g_pool[NUM_GRAPHS * HID];
__device__ float g_cnt[NUM_GRAPHS];
__device__ __align__(16) float g_cls[NUM_GRAPHS * HID];

// ---------------- CSR build ----------------
__global__ void zero_kernel() {
    int i = blockIdx.x * blockDim.x + threadIdx.x;
    if (i < N_NODES) g_deg[i] = 0;
    if (i < NUM_GRAPHS * HID) g_pool[i] = 0.f;
    if (i < NUM_GRAPHS) g_cnt[i] = 0.f;
}

__global__ void hist_kernel(const int* __restrict__ dst) {
    int e = blockIdx.x * blockDim.x + threadIdx.x;
    if (e < N_EDGES) atomicAdd(&g_deg[dst[e]], 1);
}

// block-wise inclusive scan (512/block), emits exclusive values + block sums
__global__ void scan1_kernel() {
    __shared__ int s[512];
    int tid = threadIdx.x;
    int i = blockIdx.x * 512 + tid;
    int v = (i < N_NODES) ? g_deg[i] : 0;
    s[tid] = v;
    __syncthreads();
    for (int off = 1; off < 512; off <<= 1) {
        int add = (tid >= off) ? s[tid - off] : 0;
        __syncthreads();
        s[tid] += add;
        __syncthreads();
    }
    if (i < N_NODES) g_rowptr[i] = s[tid] - v;  // exclusive
    if (tid == 511) g_bsums[blockIdx.x] = s[511];
}

__global__ void scan2_kernel(int nblk) {
    __shared__ int s[256];
    int tid = threadIdx.x;
    int v = (tid < nblk) ? g_bsums[tid] : 0;
    s[tid] = v;
    __syncthreads();
    for (int off = 1; off < 256; off <<= 1) {
        int add = (tid >= off) ? s[tid - off] : 0;
        __syncthreads();
        s[tid] += add;
        __syncthreads();
    }
    if (tid < nblk) g_bsums[tid] = s[tid] - v;  // exclusive over block sums
}

__global__ void scan3_kernel() {
    int i = blockIdx.x * blockDim.x + threadIdx.x;
    if (i < N_NODES) {
        int rp = g_rowptr[i] + g_bsums[i >> 9];
        g_rowptr[i] = rp;
        g_fill[i] = rp;
    }
    if (i == 0) g_rowptr[N_NODES] = N_EDGES;
}

__global__ void scatter_kernel(const int* __restrict__ src,
                               const int* __restrict__ dst) {
    int e = blockIdx.x * blockDim.x + threadIdx.x;
    if (e < N_EDGES) {
        int d = dst[e];
        int p = atomicAdd(&g_fill[d], 1);
        g_ssrc[p] = src[e];
    }
}

// ---------------- per-layer aggregation: h[v] = (1+eps)*x[v] + sum_in x[u] --------
__global__ void aggr_kernel(const float* __restrict__ xin_ext,
                            const float* __restrict__ eps, int layer, int use_gx) {
    int gw = (blockIdx.x * blockDim.x + threadIdx.x) >> 5;
    int lane = threadIdx.x & 31;
    if (gw >= N_NODES) return;
    const float* x = use_gx ? g_x : xin_ext;
    float ep1 = 1.0f + eps[layer];
    const float4* xv = (const float4*)x;
    float4 b = __ldg(&xv[(size_t)gw * 32 + lane]);
    float4 a0 = make_float4(b.x * ep1, b.y * ep1, b.z * ep1, b.w * ep1);
    float4 a1 = make_float4(0.f, 0.f, 0.f, 0.f);
    float4 a2 = a1, a3 = a1;
    int s = g_rowptr[gw], e = g_rowptr[gw + 1];
    int i = s;
    for (; i + 4 <= e; i += 4) {
        int s0 = g_ssrc[i], s1 = g_ssrc[i + 1], s2 = g_ssrc[i + 2], s3 = g_ssrc[i + 3];
        float4 v0 = __ldg(&xv[(size_t)s0 * 32 + lane]);
        float4 v1 = __ldg(&xv[(size_t)s1 * 32 + lane]);
        float4 v2 = __ldg(&xv[(size_t)s2 * 32 + lane]);
        float4 v3 = __ldg(&xv[(size_t)s3 * 32 + lane]);
        a0.x += v0.x; a0.y += v0.y; a0.z += v0.z; a0.w += v0.w;
        a1.x += v1.x; a1.y += v1.y; a1.z += v1.z; a1.w += v1.w;
        a2.x += v2.x; a2.y += v2.y; a2.z += v2.z; a2.w += v2.w;
        a3.x += v3.x; a3.y += v3.y; a3.z += v3.z; a3.w += v3.w;
    }
    for (; i < e; i++) {
        int s0 = g_ssrc[i];
        float4 v0 = __ldg(&xv[(size_t)s0 * 32 + lane]);
        a1.x += v0.x; a1.y += v0.y; a1.z += v0.z; a1.w += v0.w;
    }
    a0.x += a1.x + a2.x + a3.x;
    a0.y += a1.y + a2.y + a3.y;
    a0.z += a1.z + a2.z + a3.z;
    a0.w += a1.w + a2.w + a3.w;
    ((float4*)g_h)[(size_t)gw * 32 + lane] = a0;
}

// ---------------- fused MLP: g_x = relu(relu(h@W1+b1)@W2 + b2 [+h]) + xin ---------
// BM=64 rows/block, SINGLE shared tile buffer (33.8KB static), 4x8 register tile.
// W1/W2 streamed from L1/L2 via __ldg; h re-read from gmem for the MLP residual.
#define BM 64
#define HSTR 132  // padded row stride in floats

__global__ void __launch_bounds__(256)
mlp_kernel(const float* __restrict__ xin_ext,
           const float* __restrict__ W1, const float* __restrict__ b1,
           const float* __restrict__ W2, const float* __restrict__ b2,
           int add_h, int use_gx) {
    __shared__ float Bs[BM * HSTR];

    const float* xin = use_gx ? g_x : xin_ext;
    int t = threadIdx.x;
    int row0 = blockIdx.x * BM;
    int nrows = N_NODES - row0; if (nrows > BM) nrows = BM;

    // load H tile (BM x 128) into shared
    for (int i = t; i < BM * 32; i += 256) {
        int r = i >> 5, c = i & 31;
        float4 v = (r < nrows)
            ? *((const float4*)(g_h + (size_t)(row0 + r) * HID) + c)
            : make_float4(0.f, 0.f, 0.f, 0.f);
        *((float4*)&Bs[r * HSTR + c * 4]) = v;
    }
    __syncthreads();

    int tx = t & 15, ty = t >> 4;   // 16 x 16 thread grid
    int cb = tx * 8;                // 8 cols per thread
    int rb = ty * 4;                // 4 rows per thread

    float acc[4][8];
#pragma unroll
    for (int r = 0; r < 4; r++)
#pragma unroll
        for (int c = 0; c < 8; c++) acc[r][c] = 0.f;

#pragma unroll 4
    for (int k = 0; k < 128; k++) {
        float a[4];
#pragma unroll
        for (int r = 0; r < 4; r++) a[r] = Bs[(rb + r) * HSTR + k];
        float4 w0 = __ldg((const float4*)&W1[k * 128 + cb]);
        float4 w1 = __ldg((const float4*)&W1[k * 128 + cb + 4]);
        float bv[8] = {w0.x, w0.y, w0.z, w0.w, w1.x, w1.y, w1.z, w1.w};
#pragma unroll
        for (int r = 0; r < 4; r++)
#pragma unroll
            for (int c = 0; c < 8; c++) acc[r][c] += a[r] * bv[c];
    }
    __syncthreads();  // all GEMM1 reads of Bs done — safe to overwrite

    // write T = relu(acc + b1) into the SAME buffer
#pragma unroll
    for (int r = 0; r < 4; r++)
#pragma unroll
        for (int c = 0; c < 8; c++) {
            float v = acc[r][c] + __ldg(&b1[cb + c]);
            Bs[(rb + r) * HSTR + cb + c] = fmaxf(v, 0.f);
        }
    __syncthreads();

#pragma unroll
    for (int r = 0; r < 4; r++)
#pragma unroll
        for (int c = 0; c < 8; c++) acc[r][c] = 0.f;

#pragma unroll 4
    for (int k = 0; k < 128; k++) {
        float a[4];
#pragma unroll
        for (int r = 0; r < 4; r++) a[r] = Bs[(rb + r) * HSTR + k];
        float4 w0 = __ldg((const float4*)&W2[k * 128 + cb]);
        float4 w1 = __ldg((const float4*)&W2[k * 128 + cb + 4]);
        float bv[8] = {w0.x, w0.y, w0.z, w0.w, w1.x, w1.y, w1.z, w1.w};
#pragma unroll
        for (int r = 0; r < 4; r++)
#pragma unroll
            for (int c = 0; c < 8; c++) acc[r][c] += a[r] * bv[c];
    }

    // epilogue: + b2 [+ h reread] relu + xin, store
#pragma unroll
    for (int r = 0; r < 4; r++) {
        int row = rb + r;
        if (row < nrows) {
            size_t base = (size_t)(row0 + row) * HID + cb;
            float4 h0 = make_float4(0.f, 0.f, 0.f, 0.f), h1 = h0;
            if (add_h) {
                h0 = *((const float4*)(g_h + base));
                h1 = *((const float4*)(g_h + base + 4));
            }
            float hv[8] = {h0.x, h0.y, h0.z, h0.w, h1.x, h1.y, h1.z, h1.w};
            float4 xi0 = *((const float4*)(xin + base));
            float4 xi1 = *((const float4*)(xin + base + 4));
            float xv[8] = {xi0.x, xi0.y, xi0.z, xi0.w, xi1.x, xi1.y, xi1.z, xi1.w};
            float o[8];
#pragma unroll
            for (int c = 0; c < 8; c++) {
                float v = acc[r][c] + __ldg(&b2[cb + c]) + hv[c];
                o[c] = fmaxf(v, 0.f) + xv[c];
            }
            *((float4*)(g_x + base))     = make_float4(o[0], o[1], o[2], o[3]);
            *((float4*)(g_x + base + 4)) = make_float4(o[4], o[5], o[6], o[7]);
        }
    }
}

// ---------------- mean pool over sorted batch ----------------
#define POOL_CHUNK 256
__global__ void pool_kernel(const int* __restrict__ batch) {
    int d = threadIdx.x;  // 128
    int n0 = blockIdx.x * POOL_CHUNK;
    int n1 = n0 + POOL_CHUNK; if (n1 > N_NODES) n1 = N_NODES;
    int cur = batch[n0];
    float local = 0.f;
    for (int n = n0; n < n1; n++) {
        int b = batch[n];
        if (b != cur) {
            atomicAdd(&g_pool[cur * HID + d], local);
            local = 0.f; cur = b;
        }
        local += g_x[(size_t)n * HID + d];
    }
    atomicAdd(&g_pool[cur * HID + d], local);
    if (d == 0) {
        int c2 = batch[n0];
        float cl = 0.f;
        for (int n = n0; n < n1; n++) {
            int b = batch[n];
            if (b != c2) { atomicAdd(&g_cnt[c2], cl); cl = 0.f; c2 = b; }
            cl += 1.f;
        }
        atomicAdd(&g_cnt[c2], cl);
    }
}

// ---------------- classifier (two small kernels, static smem only) ----------------
__global__ void cls1_kernel(const float* __restrict__ Wc1,
                            const float* __restrict__ bc1) {
    __shared__ float Ps[128];
    int g = blockIdx.x;     // 64 blocks
    int t = threadIdx.x;    // 128 threads
    float inv = 1.f / fmaxf(g_cnt[g], 1.f);
    Ps[t] = g_pool[g * HID + t] * inv;
    __syncthreads();
    float s = bc1[t];
#pragma unroll 4
    for (int k = 0; k < 128; k++) s += Ps[k] * __ldg(&Wc1[k * 128 + t]);
    g_cls[g * HID + t] = fmaxf(s, 0.f);
}

__global__ void cls2_kernel(const float* __restrict__ Wc2,
                            const float* __restrict__ bc2,
                            float* __restrict__ out) {
    int t = threadIdx.x;  // 128 = 64 graphs * 2 classes
    int g = t >> 1, c = t & 1;
    float s = bc2[c];
#pragma unroll 4
    for (int k = 0; k < 128; k++) s += g_cls[g * HID + k] * __ldg(&Wc2[k * 2 + c]);
    out[t] = s;
}

// ---------------- launch (pure kernel launches — graph-capture safe) -------------
extern "C" void kernel_launch(void* const* d_in, const int* in_sizes, int n_in,
                              void* d_out, int out_size) {
    const float* x     = (const float*)d_in[0];
    const int*   ei    = (const int*)d_in[1];     // int32 (JAX x64 disabled)
    const int*   batch = (const int*)d_in[2];     // int32
    const float* eps   = (const float*)d_in[3];
    const float* W1    = (const float*)d_in[4];
    const float* b1    = (const float*)d_in[5];
    const float* W2    = (const float*)d_in[6];
    const float* b2    = (const float*)d_in[7];
    const float* Wc1   = (const float*)d_in[8];
    const float* bc1   = (const float*)d_in[9];
    const float* Wc2   = (const float*)d_in[10];
    const float* bc2   = (const float*)d_in[11];
    const int* src = ei;
    const int* dst = ei + N_EDGES;

    const int nblk_scan = (N_NODES + 511) / 512;  // 196

    zero_kernel<<<(N_NODES + 255) / 256, 256>>>();
    hist_kernel<<<(N_EDGES + 255) / 256, 256>>>(dst);
    scan1_kernel<<<nblk_scan, 512>>>();
    scan2_kernel<<<1, 256>>>(nblk_scan);
    scan3_kernel<<<(N_NODES + 255) / 256, 256>>>();
    scatter_kernel<<<(N_EDGES + 255) / 256, 256>>>(src, dst);

    for (int i = 0; i < NUM_LAYERS; i++) {
        int use_gx = (i > 0) ? 1 : 0;
        aggr_kernel<<<(N_NODES + 7) / 8, 256>>>(x, eps, i, use_gx);
        mlp_kernel<<<(N_NODES + BM - 1) / BM, 256>>>(
            x,
            W1 + (size_t)i * HID * HID, b1 + (size_t)i * HID,
            W2 + (size_t)i * HID * HID, b2 + (size_t)i * HID,
            (i > 0) ? 1 : 0, use_gx);
    }

    pool_kernel<<<(N_NODES + POOL_CHUNK - 1) / POOL_CHUNK, 128>>>(batch);
    cls1_kernel<<<NUM_GRAPHS, 128>>>(Wc1, bc1);
    cls2_kernel<<<1, 128>>>(Wc2, bc2, (float*)d_out);
}